// round 3
// baseline (speedup 1.0000x reference)
#include <cuda_runtime.h>
#include <cuda_fp16.h>
#include <math.h>
#include <stdint.h>

#define NN 100000
#define NE 1600000
#define SCAN_NBLK 98                  // ceil(NN/1024)
#define GEMM_BLKS ((NN + 127) / 128)  // 782

// ---------------- scratch (static device globals; no allocation) ----------------
__device__ __align__(16) __half g_h1h[(size_t)NN * 128]; // layer-1 features fp16
__device__ __align__(16) __half g_w1h[128 * 128];        // W1 in fp16
__device__ __align__(16) __half g_w2h[(size_t)NN * 40];  // layer-2 features fp16
__device__ float g_ai1[NN * 8];
__device__ float g_aj1[NN * 8];
__device__ float g_z[(size_t)NN * 128];     // elu(agg1) output
__device__ float g_ai2[NN];
__device__ float g_aj2[NN];
__device__ int   g_deg[NN];
__device__ int   g_rowptr[NN + 1];
__device__ int   g_cur[NN];
__device__ int   g_csr[NE];
__device__ int   g_bsums[SCAN_NBLK];

// ---------------- f32x2 packed-FMA helpers (SASS FFMA2) ----------------
__device__ __forceinline__ void ffma2(unsigned long long& acc,
                                      unsigned long long a, unsigned long long b) {
    asm("fma.rn.f32x2 %0, %1, %2, %0;" : "+l"(acc) : "l"(a), "l"(b));
}
__device__ __forceinline__ unsigned long long pack2(float x, float y) {
    unsigned long long v;
    asm("mov.b64 %0, {%1, %2};" : "=l"(v)
        : "r"(__float_as_uint(x)), "r"(__float_as_uint(y)));
    return v;
}
__device__ __forceinline__ float2 unpack2(unsigned long long v) {
    unsigned lo, hi;
    asm("mov.b64 {%0, %1}, %2;" : "=r"(lo), "=r"(hi) : "l"(v));
    return make_float2(__uint_as_float(lo), __uint_as_float(hi));
}

// ---------------- mma helpers ----------------
__device__ __forceinline__ void ldsm4(uint32_t& r0, uint32_t& r1, uint32_t& r2,
                                      uint32_t& r3, uint32_t addr) {
    asm volatile("ldmatrix.sync.aligned.m8n8.x4.shared.b16 {%0,%1,%2,%3}, [%4];"
                 : "=r"(r0), "=r"(r1), "=r"(r2), "=r"(r3) : "r"(addr));
}
__device__ __forceinline__ void mma16816(float& d0, float& d1, float& d2, float& d3,
                                         uint32_t a0, uint32_t a1, uint32_t a2, uint32_t a3,
                                         uint32_t b0, uint32_t b1) {
    asm volatile("mma.sync.aligned.m16n8k16.row.col.f32.f16.f16.f32 "
                 "{%0,%1,%2,%3}, {%4,%5,%6,%7}, {%8,%9}, {%0,%1,%2,%3};"
                 : "+f"(d0), "+f"(d1), "+f"(d2), "+f"(d3)
                 : "r"(a0), "r"(a1), "r"(a2), "r"(a3), "r"(b0), "r"(b1));
}

// ---------------- CSR build ----------------
__global__ void k_zero_deg() {
    int i = blockIdx.x * blockDim.x + threadIdx.x;
    if (i < NN) g_deg[i] = 0;
}

__global__ void k_hist(const int* __restrict__ dst) {
    int i = blockIdx.x * blockDim.x + threadIdx.x;
    if (i < NE) atomicAdd(&g_deg[dst[i]], 1);
}

__global__ void k_scan1() {
    __shared__ int sh[1024];
    int i = blockIdx.x * 1024 + threadIdx.x;
    int v = (i < NN) ? g_deg[i] : 0;
    sh[threadIdx.x] = v;
    __syncthreads();
    for (int off = 1; off < 1024; off <<= 1) {
        int t = (threadIdx.x >= off) ? sh[threadIdx.x - off] : 0;
        __syncthreads();
        sh[threadIdx.x] += t;
        __syncthreads();
    }
    if (i < NN) g_rowptr[i] = sh[threadIdx.x] - v;   // exclusive
    if (threadIdx.x == 1023) g_bsums[blockIdx.x] = sh[1023];
}

__global__ void k_scan2() {   // 1 warp, shuffle scan of 98 block sums
    int lane = threadIdx.x;
    int carry = 0;
    for (int b = 0; b < SCAN_NBLK; b += 32) {
        int idx = b + lane;
        int orig = (idx < SCAN_NBLK) ? g_bsums[idx] : 0;
        int v = orig;
        #pragma unroll
        for (int off = 1; off < 32; off <<= 1) {
            int t = __shfl_up_sync(0xffffffffu, v, off);
            if (lane >= off) v += t;
        }
        if (idx < SCAN_NBLK) g_bsums[idx] = carry + v - orig;  // exclusive
        carry += __shfl_sync(0xffffffffu, v, 31);
    }
    if (lane == 0) g_rowptr[NN] = carry;
}

__global__ void k_scan3() {   // add block offsets + init g_cur
    int i = blockIdx.x * 1024 + threadIdx.x;
    if (i < NN) {
        int v = g_rowptr[i] + g_bsums[blockIdx.x];
        g_rowptr[i] = v;
        g_cur[i] = v;
    }
}

__global__ void k_scatter(const int* __restrict__ src, const int* __restrict__ dst) {
    int i = blockIdx.x * blockDim.x + threadIdx.x;
    if (i < NE) {
        int pos = atomicAdd(&g_cur[dst[i]], 1);
        g_csr[pos] = src[i];
    }
}

// ---------------- convert W1 to fp16 ----------------
__global__ void k_cvtw1(const float* __restrict__ W1) {
    int i = blockIdx.x * blockDim.x + threadIdx.x;
    if (i < 128 * 128) g_w1h[i] = __float2half_rn(W1[i]);
}

// ---------------- GEMM1 (HMMA): h1 = x @ W1^T + b1 -> fp16 ----------------
// 256 threads = 8 warps; block tile 128x128, warp tile 16 rows x 128 cols; K=128.
__global__ void __launch_bounds__(256, 1)
k_gemm1(const float* __restrict__ x, const float* __restrict__ b1) {
    extern __shared__ __half sm[];
    __half* As = sm;             // [128][136] rows x k
    __half* Bs = sm + 128 * 136; // [128][136] n x k
    const int tid  = threadIdx.x;
    const int lane = tid & 31;
    const int warp = tid >> 5;
    const int r0   = blockIdx.x * 128;

    // fill A: x fp32 -> fp16
    {
        const int lr = tid >> 1;
        const int khalf = (tid & 1) * 64;
        int gr = min(r0 + lr, NN - 1);
        const float4* xr = (const float4*)(x + (size_t)gr * 128 + khalf);
        #pragma unroll
        for (int i = 0; i < 16; ++i) {
            float4 v = xr[i];
            __half2 h0 = __floats2half2_rn(v.x, v.y);
            __half2 h1 = __floats2half2_rn(v.z, v.w);
            uint2 pk;
            pk.x = *(unsigned*)&h0; pk.y = *(unsigned*)&h1;
            *(uint2*)(As + lr * 136 + khalf + i * 4) = pk;
        }
    }
    // fill B: W1 fp16 copy
    {
        const int lr = tid >> 1;
        const int khalf = (tid & 1) * 64;
        const uint4* wr = (const uint4*)(g_w1h + lr * 128 + khalf);
        #pragma unroll
        for (int i = 0; i < 8; ++i)
            *(uint4*)(Bs + lr * 136 + khalf + i * 8) = wr[i];
    }
    __syncthreads();

    const uint32_t As_b = (uint32_t)__cvta_generic_to_shared(As);
    const uint32_t Bs_b = (uint32_t)__cvta_generic_to_shared(Bs);
    const int wr0 = warp * 16;

    const uint32_t aPtr = As_b +
        (((wr0 + (lane & 7) + ((lane >> 3) & 1) * 8) * 136) + (lane >> 4) * 8) * 2;
    const uint32_t bPtr = Bs_b +
        ((((lane & 7) + (lane >> 4) * 8) * 136) + ((lane >> 3) & 1) * 8) * 2;

    float c[16][4];
    #pragma unroll
    for (int t = 0; t < 16; ++t)
        #pragma unroll
        for (int j = 0; j < 4; ++j) c[t][j] = 0.f;

    #pragma unroll
    for (int kb = 0; kb < 128; kb += 16) {
        uint32_t a0, a1, a2, a3;
        ldsm4(a0, a1, a2, a3, aPtr + kb * 2);
        #pragma unroll
        for (int nt = 0; nt < 8; ++nt) {
            uint32_t b0, b1, b2, b3;
            ldsm4(b0, b1, b2, b3, bPtr + nt * 16 * 136 * 2 + kb * 2);
            mma16816(c[2*nt][0], c[2*nt][1], c[2*nt][2], c[2*nt][3],
                     a0, a1, a2, a3, b0, b1);
            mma16816(c[2*nt+1][0], c[2*nt+1][1], c[2*nt+1][2], c[2*nt+1][3],
                     a0, a1, a2, a3, b2, b3);
        }
    }

    // epilogue: + bias, store fp16
    const int rr0 = r0 + wr0 + (lane >> 2);
    const int rr1 = rr0 + 8;
    #pragma unroll
    for (int t = 0; t < 16; ++t) {
        int col0 = t * 8 + (lane & 3) * 2;
        float bv0 = __ldg(&b1[col0]);
        float bv1 = __ldg(&b1[col0 + 1]);
        if (rr0 < NN) {
            __half2 h = __floats2half2_rn(c[t][0] + bv0, c[t][1] + bv1);
            *(unsigned*)(g_h1h + (size_t)rr0 * 128 + col0) = *(unsigned*)&h;
        }
        if (rr1 < NN) {
            __half2 h = __floats2half2_rn(c[t][2] + bv0, c[t][3] + bv1);
            *(unsigned*)(g_h1h + (size_t)rr1 * 128 + col0) = *(unsigned*)&h;
        }
    }
}

// ---------------- attention scalars layer 1 (from fp16 h1) ----------------
// one warp per node; lane owns 4 channels; head = lane>>2
__global__ void k_att1(const float* __restrict__ att1) {
    int gw = (blockIdx.x * blockDim.x + threadIdx.x) >> 5;
    if (gw >= NN) return;
    const int lane = threadIdx.x & 31;
    const int head = lane >> 2;
    const int ch   = (lane & 3) * 4;

    uint2 pk = *(const uint2*)(g_h1h + (size_t)gw * 128 + lane * 4);
    float2 f0 = __half22float2(*(const __half2*)&pk.x);
    float2 f1 = __half22float2(*(const __half2*)&pk.y);
    const float* ati = att1 + head * 32 + ch;
    const float* atj = ati + 16;
    float ai = f0.x * ati[0] + f0.y * ati[1] + f1.x * ati[2] + f1.y * ati[3];
    float aj = f0.x * atj[0] + f0.y * atj[1] + f1.x * atj[2] + f1.y * atj[3];
    ai += __shfl_xor_sync(0xffffffffu, ai, 1);
    ai += __shfl_xor_sync(0xffffffffu, ai, 2);
    aj += __shfl_xor_sync(0xffffffffu, aj, 1);
    aj += __shfl_xor_sync(0xffffffffu, aj, 2);
    if ((lane & 3) == 0) {
        g_ai1[gw * 8 + head] = ai;
        g_aj1[gw * 8 + head] = aj;
    }
}

// ---------------- Aggregation layer 1 (+ bias1 + ELU) -> g_z ----------------
__device__ __forceinline__ void edge1_acc(int s, float ai, int lane, int head,
                                          float4& acc, float& den) {
    float aj = __ldg(&g_aj1[s * 8 + head]);
    float e = ai + aj;
    e = fmaxf(e, 0.2f * e);
    float ex = __expf(e);
    uint2 rv = *(const uint2*)(g_h1h + (size_t)s * 128 + lane * 4);
    float2 f0 = __half22float2(*(const __half2*)&rv.x);
    float2 f1 = __half22float2(*(const __half2*)&rv.y);
    acc.x = fmaf(ex, f0.x, acc.x);
    acc.y = fmaf(ex, f0.y, acc.y);
    acc.z = fmaf(ex, f1.x, acc.z);
    acc.w = fmaf(ex, f1.y, acc.w);
    den += ex;
}

__global__ void k_agg1(const float* __restrict__ bias1) {
    int gw = (blockIdx.x * blockDim.x + threadIdx.x) >> 5;
    if (gw >= NN) return;
    const int lane = threadIdx.x & 31;
    const int head = lane >> 2;

    const float ai = __ldg(&g_ai1[gw * 8 + head]);
    float4 acc = make_float4(0.f, 0.f, 0.f, 0.f);
    float den = 0.f;

    edge1_acc(gw, ai, lane, head, acc, den);   // self loop

    int i = g_rowptr[gw];
    const int end = g_rowptr[gw + 1];
    for (; i + 4 <= end; i += 4) {
        int s0 = __ldg(&g_csr[i + 0]);
        int s1 = __ldg(&g_csr[i + 1]);
        int s2 = __ldg(&g_csr[i + 2]);
        int s3 = __ldg(&g_csr[i + 3]);
        edge1_acc(s0, ai, lane, head, acc, den);
        edge1_acc(s1, ai, lane, head, acc, den);
        edge1_acc(s2, ai, lane, head, acc, den);
        edge1_acc(s3, ai, lane, head, acc, den);
    }
    for (; i < end; ++i)
        edge1_acc(__ldg(&g_csr[i]), ai, lane, head, acc, den);

    float inv = 1.f / (den + 1e-16f);
    float4 bb = *(const float4*)(bias1 + lane * 4);
    float o0 = fmaf(acc.x, inv, bb.x);
    float o1 = fmaf(acc.y, inv, bb.y);
    float o2 = fmaf(acc.z, inv, bb.z);
    float o3 = fmaf(acc.w, inv, bb.w);
    o0 = o0 > 0.f ? o0 : expm1f(o0);
    o1 = o1 > 0.f ? o1 : expm1f(o1);
    o2 = o2 > 0.f ? o2 : expm1f(o2);
    o3 = o3 > 0.f ? o3 : expm1f(o3);
    *(float4*)(g_z + (size_t)gw * 128 + lane * 4) = make_float4(o0, o1, o2, o3);
}

// ---------------- GEMM2: w2 = z @ W2^T + b2 (fp16 out) ; fused a_i2/a_j2 ----------------
__global__ void __launch_bounds__(256)
k_gemm2(const float* __restrict__ W2, const float* __restrict__ b2,
        const float* __restrict__ att2) {
    __shared__ float Zs[64 * 132];   // Zs[k][row]
    __shared__ float Ws[64 * 40];    // Ws[k][col]
    const int tid = threadIdx.x;
    const int tx = tid & 7;          // 5 cols
    const int ty = tid >> 3;         // 4 rows
    const int r0 = blockIdx.x * 128;

    unsigned long long acc[2][5];    // row pairs (0,1),(2,3) x 5 cols
    #pragma unroll
    for (int p = 0; p < 2; ++p)
        #pragma unroll
        for (int c = 0; c < 5; ++c) acc[p][c] = 0ull;

    const int lr = tid >> 1;
    const int khalf = (tid & 1) * 32;

    for (int kc = 0; kc < 128; kc += 64) {
        __syncthreads();
        {
            int gr = min(r0 + lr, NN - 1);
            const float4* zr = (const float4*)(g_z + (size_t)gr * 128 + kc + khalf);
            #pragma unroll
            for (int i = 0; i < 8; ++i) {
                float4 v = zr[i];
                int k = khalf + i * 4;
                Zs[(k + 0) * 132 + lr] = v.x;
                Zs[(k + 1) * 132 + lr] = v.y;
                Zs[(k + 2) * 132 + lr] = v.z;
                Zs[(k + 3) * 132 + lr] = v.w;
            }
        }
        for (int i = tid; i < 40 * 64; i += 256) {
            int o = i >> 6, k = i & 63;
            Ws[k * 40 + o] = W2[(size_t)o * 128 + kc + k];
        }
        __syncthreads();

        #pragma unroll 2
        for (int k = 0; k < 64; ++k) {
            float4 a = *(const float4*)(Zs + k * 132 + ty * 4);
            unsigned long long a01 = pack2(a.x, a.y);
            unsigned long long a23 = pack2(a.z, a.w);
            const float* wrow = Ws + k * 40 + tx * 5;
            #pragma unroll
            for (int c = 0; c < 5; ++c) {
                unsigned long long ww = pack2(wrow[c], wrow[c]);
                ffma2(acc[0][c], a01, ww);
                ffma2(acc[1][c], a23, ww);
            }
        }
    }

    float bo[5], ati[5], atj[5];
    #pragma unroll
    for (int c = 0; c < 5; ++c) {
        bo[c]  = b2[tx * 5 + c];
        ati[c] = att2[tx * 5 + c];
        atj[c] = att2[40 + tx * 5 + c];
    }
    #pragma unroll
    for (int j = 0; j < 4; ++j) {
        int r = r0 + ty * 4 + j;
        float pi = 0.f, pj = 0.f;
        float v[5];
        #pragma unroll
        for (int c = 0; c < 5; ++c) {
            float2 f = unpack2(acc[j >> 1][c]);
            v[c] = ((j & 1) ? f.y : f.x) + bo[c];
            pi = fmaf(v[c], ati[c], pi);
            pj = fmaf(v[c], atj[c], pj);
        }
        #pragma unroll
        for (int off = 1; off < 8; off <<= 1) {
            pi += __shfl_xor_sync(0xffffffffu, pi, off);
            pj += __shfl_xor_sync(0xffffffffu, pj, off);
        }
        if (r < NN) {
            #pragma unroll
            for (int c = 0; c < 5; ++c)
                g_w2h[(size_t)r * 40 + tx * 5 + c] = __float2half_rn(v[c]);
            if (tx == 0) { g_ai2[r] = pi; g_aj2[r] = pj; }
        }
    }
}

// ---------------- Aggregation layer 2 + bias2 + fused log_softmax ----------------
// one warp per node; lanes 0..19 each own 2 channels (half2 gather)
__device__ __forceinline__ void edge2_acc(int s, float ai, int lane, bool act,
                                          float2& acc, float& den) {
    float aj = __ldg(&g_aj2[s]);
    float e = ai + aj;
    e = fmaxf(e, 0.2f * e);
    float ex = __expf(e);
    if (act) {
        unsigned pk = *(const unsigned*)(g_w2h + (size_t)s * 40 + lane * 2);
        float2 f = __half22float2(*(const __half2*)&pk);
        acc.x = fmaf(ex, f.x, acc.x);
        acc.y = fmaf(ex, f.y, acc.y);
    }
    den += ex;
}

__global__ void k_agg2(const float* __restrict__ bias2, float* __restrict__ out) {
    int gw = (blockIdx.x * blockDim.x + threadIdx.x) >> 5;
    if (gw >= NN) return;
    const int lane = threadIdx.x & 31;
    const bool act = lane < 20;

    const float ai = __ldg(&g_ai2[gw]);
    float2 acc = make_float2(0.f, 0.f);
    float den = 0.f;

    edge2_acc(gw, ai, lane, act, acc, den);   // self loop

    int i = g_rowptr[gw];
    const int end = g_rowptr[gw + 1];
    for (; i + 4 <= end; i += 4) {
        int s0 = __ldg(&g_csr[i + 0]);
        int s1 = __ldg(&g_csr[i + 1]);
        int s2 = __ldg(&g_csr[i + 2]);
        int s3 = __ldg(&g_csr[i + 3]);
        edge2_acc(s0, ai, lane, act, acc, den);
        edge2_acc(s1, ai, lane, act, acc, den);
        edge2_acc(s2, ai, lane, act, acc, den);
        edge2_acc(s3, ai, lane, act, acc, den);
    }
    for (; i < end; ++i)
        edge2_acc(__ldg(&g_csr[i]), ai, lane, act, acc, den);

    float inv = 1.f / (den + 1e-16f);
    float o0 = -INFINITY, o1 = -INFINITY;
    if (act) {
        o0 = fmaf(acc.x, inv, bias2[lane * 2]);
        o1 = fmaf(acc.y, inv, bias2[lane * 2 + 1]);
    }

    float m = fmaxf(o0, o1);
    #pragma unroll
    for (int off = 16; off; off >>= 1)
        m = fmaxf(m, __shfl_xor_sync(0xffffffffu, m, off));
    float s = act ? (expf(o0 - m) + expf(o1 - m)) : 0.f;
    #pragma unroll
    for (int off = 16; off; off >>= 1)
        s += __shfl_xor_sync(0xffffffffu, s, off);
    float lse = m + logf(s);

    if (act) {
        out[(size_t)gw * 40 + lane * 2]     = o0 - lse;
        out[(size_t)gw * 40 + lane * 2 + 1] = o1 - lse;
    }
}

// ---------------- launch ----------------
extern "C" void kernel_launch(void* const* d_in, const int* in_sizes, int n_in,
                              void* d_out, int out_size) {
    const float* x     = (const float*)d_in[0];
    const int*   ei    = (const int*)d_in[1];
    const float* W1    = (const float*)d_in[2];
    const float* b1    = (const float*)d_in[3];
    const float* att1  = (const float*)d_in[4];
    const float* bias1 = (const float*)d_in[5];
    const float* W2    = (const float*)d_in[6];
    const float* b2    = (const float*)d_in[7];
    const float* att2  = (const float*)d_in[8];
    const float* bias2 = (const float*)d_in[9];
    float* out = (float*)d_out;

    const int* src = ei;
    const int* dst = ei + NE;

    const int smem1 = 2 * 128 * 136 * (int)sizeof(__half);   // 69632 B
    cudaFuncSetAttribute(k_gemm1, cudaFuncAttributeMaxDynamicSharedMemorySize, smem1);

    // CSR build
    k_zero_deg<<<(NN + 255) / 256, 256>>>();
    k_hist<<<(NE + 255) / 256, 256>>>(dst);
    k_scan1<<<SCAN_NBLK, 1024>>>();
    k_scan2<<<1, 32>>>();
    k_scan3<<<SCAN_NBLK, 1024>>>();
    k_scatter<<<(NE + 255) / 256, 256>>>(src, dst);

    // layer 1
    k_cvtw1<<<64, 256>>>(W1);
    k_gemm1<<<GEMM_BLKS, 256, smem1>>>(x, b1);
    k_att1<<<(NN * 32 + 255) / 256, 256>>>(att1);
    k_agg1<<<(NN * 32 + 255) / 256, 256>>>(bias1);

    // layer 2
    k_gemm2<<<GEMM_BLKS, 256>>>(W2, b2, att2);
    k_agg2<<<(NN * 32 + 255) / 256, 256>>>(bias2, out);
}